// round 15
// baseline (speedup 1.0000x reference)
#include <cuda_runtime.h>
#include <math.h>

#define IMG 1024
#define NPATCH 16384
#define NTHREADS (NPATCH * 2)

#define GIX(i,j) (((i)<(j)) ? ((i)*6+(j)) : ((j)*6+(i)))

__global__ __launch_bounds__(128)
void curvature_kernel(const float* __restrict__ depth, float* __restrict__ out)
{
    const int t = blockIdx.x * 128 + threadIdx.x;
    const int pidx = t >> 1;        // patch index (2 lanes per patch)
    const int u = t & 1;            // lane-in-group: handles rows 4u..4u+3

    // ---- patch remap: interior patches first, boundary clustered at the end ----
    int pi, pj;
    const bool interior = (pidx < 127 * 127);
    if (interior) {
        const int r = pidx / 127;
        pi = 1 + r;
        pj = 1 + (pidx - r * 127);
    } else {
        const int b = pidx - 127 * 127;
        if (b < 128) { pi = 0; pj = b; }
        else { pi = b - 127; pj = 0; }
    }

    const int yc = 8 * pi + 3, xc = 8 * pj + 3;
    const float d36 = __ldg(&depth[yc * IMG + xc]);   // same addr across pair -> broadcast

    // ---- partial z-moments over this lane's 4 rows ----
    float Z1_10=0.f,Z1_01=0.f,Z1_20=0.f,Z1_11=0.f,Z1_02=0.f;
    float Z1_30=0.f,Z1_21=0.f,Z1_12=0.f,Z1_03=0.f;
    float Z2_00=0.f,Z2_10=0.f,Z2_01=0.f,Z2_20=0.f,Z2_11=0.f,Z2_02=0.f;
    float Z3_00=0.f,Z3_10=0.f,Z3_01=0.f;
    float Z4_00=0.f;

    if (interior) {
        const int rowbase = (8 * pi - 1) * IMG + 8 * pj;   // col 8pj, 16B aligned
        #pragma unroll
        for (int rr = 0; rr < 4; rr++) {
            const int r = 4 * u + rr;
            const float zm = __ldg(depth + rowbase - 1 + r * IMG);
            const float4 fa = __ldg(reinterpret_cast<const float4*>(depth + rowbase + r * IMG));
            const float4 fb = __ldg(reinterpret_cast<const float4*>(depth + rowbase + 4 + r * IMG));

            float z[8];
            z[0] = zm   - d36; z[1] = fa.x - d36; z[2] = fa.y - d36; z[3] = fa.z - d36;
            z[4] = fa.w - d36; z[5] = fb.x - d36; z[6] = fb.y - d36; z[7] = fb.z - d36;
            float z2[8], z3[8];
            #pragma unroll
            for (int c = 0; c < 8; c++) { z2[c] = z[c] * z[c]; z3[c] = z2[c] * z[c]; }

            float s1 = 0.f, s1a = 0.f, s1a2 = 0.f, s1a3 = 0.f;
            float s2 = 0.f, s2a = 0.f, s2a2 = 0.f;
            float s3 = 0.f, s3a = 0.f, s4 = 0.f;
            #pragma unroll
            for (int c = 0; c < 8; c++) {
                const float A = (float)(c - 4);
                const float A2 = A * A, A3 = A2 * A;
                s1   += z[c];
                s1a  = fmaf(A,  z[c], s1a);
                s1a2 = fmaf(A2, z[c], s1a2);
                s1a3 = fmaf(A3, z[c], s1a3);
                s2   += z2[c];
                s2a  = fmaf(A,  z2[c], s2a);
                s2a2 = fmaf(A2, z2[c], s2a2);
                s3   += z3[c];
                s3a  = fmaf(A,  z3[c], s3a);
                s4   = fmaf(z2[c], z2[c], s4);
            }

            const float B = (float)(r - 4);
            const float B2 = B * B, B3 = B2 * B;
            Z1_10 += s1a;                 Z1_01 = fmaf(B,  s1,   Z1_01);
            Z1_20 += s1a2;                Z1_11 = fmaf(B,  s1a,  Z1_11);
            Z1_02 = fmaf(B2, s1,  Z1_02); Z1_30 += s1a3;
            Z1_21 = fmaf(B,  s1a2, Z1_21); Z1_12 = fmaf(B2, s1a, Z1_12);
            Z1_03 = fmaf(B3, s1,  Z1_03);
            Z2_00 += s2;                  Z2_10 += s2a;
            Z2_01 = fmaf(B,  s2,  Z2_01); Z2_20 += s2a2;
            Z2_11 = fmaf(B,  s2a, Z2_11); Z2_02 = fmaf(B2, s2, Z2_02);
            Z3_00 += s3;                  Z3_10 += s3a;
            Z3_01 = fmaf(B,  s3,  Z3_01); Z4_00 += s4;
        }
    } else {
        #pragma unroll
        for (int rr = 0; rr < 4; rr++) {
            const int r = 4 * u + rr;
            const int R = 8 * pi + r;
            float z[8];
            #pragma unroll
            for (int c = 0; c < 8; c++) {
                const int C = 8 * pj + c;
                z[c] = (R == 0 || C == 0) ? 0.f
                     : __ldg(&depth[(R - 1) * IMG + (C - 1)]) - d36;
            }
            float z2[8], z3[8];
            #pragma unroll
            for (int c = 0; c < 8; c++) { z2[c] = z[c] * z[c]; z3[c] = z2[c] * z[c]; }

            float s1 = 0.f, s1a = 0.f, s1a2 = 0.f, s1a3 = 0.f;
            float s2 = 0.f, s2a = 0.f, s2a2 = 0.f;
            float s3 = 0.f, s3a = 0.f, s4 = 0.f;
            #pragma unroll
            for (int c = 0; c < 8; c++) {
                const float A = (float)(c - 4);
                const float A2 = A * A, A3 = A2 * A;
                s1   += z[c];
                s1a  = fmaf(A,  z[c], s1a);
                s1a2 = fmaf(A2, z[c], s1a2);
                s1a3 = fmaf(A3, z[c], s1a3);
                s2   += z2[c];
                s2a  = fmaf(A,  z2[c], s2a);
                s2a2 = fmaf(A2, z2[c], s2a2);
                s3   += z3[c];
                s3a  = fmaf(A,  z3[c], s3a);
                s4   = fmaf(z2[c], z2[c], s4);
            }

            const float B = (float)(r - 4);
            const float B2 = B * B, B3 = B2 * B;
            Z1_10 += s1a;                 Z1_01 = fmaf(B,  s1,   Z1_01);
            Z1_20 += s1a2;                Z1_11 = fmaf(B,  s1a,  Z1_11);
            Z1_02 = fmaf(B2, s1,  Z1_02); Z1_30 += s1a3;
            Z1_21 = fmaf(B,  s1a2, Z1_21); Z1_12 = fmaf(B2, s1a, Z1_12);
            Z1_03 = fmaf(B3, s1,  Z1_03);
            Z2_00 += s2;                  Z2_10 += s2a;
            Z2_01 = fmaf(B,  s2,  Z2_01); Z2_20 += s2a2;
            Z2_11 = fmaf(B,  s2a, Z2_11); Z2_02 = fmaf(B2, s2, Z2_02);
            Z3_00 += s3;                  Z3_10 += s3a;
            Z3_01 = fmaf(B,  s3,  Z3_01); Z4_00 += s4;
        }
    }

    // ---- single-step butterfly across the 2-lane pair ----
    #define BFLY(v) do { v += __shfl_xor_sync(0xFFFFFFFFu, v, 1); } while (0)
    BFLY(Z1_10); BFLY(Z1_01); BFLY(Z1_20); BFLY(Z1_11); BFLY(Z1_02);
    BFLY(Z1_30); BFLY(Z1_21); BFLY(Z1_12); BFLY(Z1_03);
    BFLY(Z2_00); BFLY(Z2_10); BFLY(Z2_01); BFLY(Z2_20); BFLY(Z2_11); BFLY(Z2_02);
    BFLY(Z3_00); BFLY(Z3_10); BFLY(Z3_01);
    BFLY(Z4_00);
    #undef BFLY

    // ---- assemble scatter blocks (both lanes redundantly) ----
    float S[21], E[18];
    float T00, T01, T02, T11, T12, T22;

    if (interior) {
        S[0]  = 3616.f;        S[1]  = 1936.f;        S[2]  = Z2_20;
        S[3]  = 512.f;         S[4]  = 2.f * Z1_30;   S[5]  = 2.f * Z1_21;
        S[6]  = 3616.f;        S[7]  = Z2_02;         S[8]  = 512.f;
        S[9]  = 2.f * Z1_12;   S[10] = 2.f * Z1_03;   S[11] = Z4_00;
        S[12] = 2.f * Z2_11;   S[13] = 2.f * Z3_10;   S[14] = 2.f * Z3_01;
        S[15] = 7744.f;        S[16] = 4.f * Z1_21;   S[17] = 4.f * Z1_12;
        S[18] = 4.f * Z2_20;   S[19] = 4.f * Z2_11;   S[20] = 4.f * Z2_02;

        E[0]  = -1024.f;       E[1]  = -352.f;        E[2]  = 2.f * Z1_20;
        E[3]  = -352.f;        E[4]  = -1024.f;       E[5]  = 2.f * Z1_02;
        E[6]  = 2.f * Z2_10;   E[7]  = 2.f * Z2_01;   E[8]  = 2.f * Z3_00;
        E[9]  = -704.f;        E[10] = -704.f;        E[11] = 4.f * Z1_11;
        E[12] = 4.f * Z1_20;   E[13] = 4.f * Z1_11;   E[14] = 4.f * Z2_10;
        E[15] = 4.f * Z1_11;   E[16] = 4.f * Z1_02;   E[17] = 4.f * Z2_01;

        T00 = 1408.f;  T01 = 64.f;  T02 = 4.f * Z1_10;
        T11 = 1408.f;  T12 = 4.f * Z1_01;  T22 = 4.f * Z2_00;
    } else {
        const bool top = (pi == 0), lft = (pj == 0);
        const float SA0 = lft ? 7.f : 8.f,  SA1 = lft ? 0.f : -4.f, SA2 = lft ? 28.f : 44.f;
        const float SA3 = lft ? 0.f : -64.f, SA4 = lft ? 196.f : 452.f;
        const float SB0 = top ? 7.f : 8.f,  SB1 = top ? 0.f : -4.f, SB2 = top ? 28.f : 44.f;
        const float SB3 = top ? 0.f : -64.f, SB4 = top ? 196.f : 452.f;

        S[0]  = SA4 * SB0;       S[1]  = SA2 * SB2;       S[2]  = Z2_20;
        S[3]  = 2.f * SA3 * SB1; S[4]  = 2.f * Z1_30;     S[5]  = 2.f * Z1_21;
        S[6]  = SA0 * SB4;       S[7]  = Z2_02;           S[8]  = 2.f * SA1 * SB3;
        S[9]  = 2.f * Z1_12;     S[10] = 2.f * Z1_03;     S[11] = Z4_00;
        S[12] = 2.f * Z2_11;     S[13] = 2.f * Z3_10;     S[14] = 2.f * Z3_01;
        S[15] = 4.f * SA2 * SB2; S[16] = 4.f * Z1_21;     S[17] = 4.f * Z1_12;
        S[18] = 4.f * Z2_20;     S[19] = 4.f * Z2_11;     S[20] = 4.f * Z2_02;

        E[0]  = 2.f * SA3 * SB0; E[1]  = 2.f * SA2 * SB1; E[2]  = 2.f * Z1_20;
        E[3]  = 2.f * SA1 * SB2; E[4]  = 2.f * SA0 * SB3; E[5]  = 2.f * Z1_02;
        E[6]  = 2.f * Z2_10;     E[7]  = 2.f * Z2_01;     E[8]  = 2.f * Z3_00;
        E[9]  = 4.f * SA2 * SB1; E[10] = 4.f * SA1 * SB2; E[11] = 4.f * Z1_11;
        E[12] = 4.f * Z1_20;     E[13] = 4.f * Z1_11;     E[14] = 4.f * Z2_10;
        E[15] = 4.f * Z1_11;     E[16] = 4.f * Z1_02;     E[17] = 4.f * Z2_01;

        T00 = 4.f * SA2 * SB0; T01 = 4.f * SA1 * SB1; T02 = 4.f * Z1_10;
        T11 = 4.f * SA0 * SB2; T12 = 4.f * Z1_01;     T22 = 4.f * Z2_00;

        // exact rank-1 pad correction
        const float n = (top && lft) ? 15.f : 8.f;
        const float P1 = -(float)xc, P2 = -(float)yc, P3 = -d36;
        const float dd[6] = { P1*P1, P2*P2, P3*P3, 2.f*P1*P2, 2.f*P1*P3, 2.f*P2*P3 };
        const float lv[3] = { 2.f*P1, 2.f*P2, 2.f*P3 };
        {
            int q = 0;
            #pragma unroll
            for (int f = 0; f < 6; f++) {
                const float nf = n * dd[f];
                #pragma unroll
                for (int g2 = f; g2 < 6; g2++) { S[q] = fmaf(nf, dd[g2], S[q]); q++; }
                E[f * 3 + 0] = fmaf(nf, lv[0], E[f * 3 + 0]);
                E[f * 3 + 1] = fmaf(nf, lv[1], E[f * 3 + 1]);
                E[f * 3 + 2] = fmaf(nf, lv[2], E[f * 3 + 2]);
            }
        }
        T00 = fmaf(n * lv[0], lv[0], T00); T01 = fmaf(n * lv[0], lv[1], T01);
        T02 = fmaf(n * lv[0], lv[2], T02); T11 = fmaf(n * lv[1], lv[1], T11);
        T12 = fmaf(n * lv[1], lv[2], T12); T22 = fmaf(n * lv[2], lv[2], T22);
    }

    // =================== tail (redundant on both lanes) ===================
    const float c00 = T11 * T22 - T12 * T12;
    const float c01 = T02 * T12 - T01 * T22;
    const float c02 = T01 * T12 - T02 * T11;
    const float det = T00 * c00 + T01 * c01 + T02 * c02;
    const float id = __fdividef(1.0f, det);
    const float I00 = c00 * id, I01 = c01 * id, I02 = c02 * id;
    const float I11 = (T00 * T22 - T02 * T02) * id;
    const float I12 = (T01 * T02 - T00 * T12) * id;
    const float I22 = (T00 * T11 - T01 * T01) * id;

    float a[36];
    {
        int q = 0;
        #pragma unroll
        for (int f = 0; f < 6; f++) {
            const float e0 = E[f * 3 + 0], e1 = E[f * 3 + 1], e2 = E[f * 3 + 2];
            const float w0 = e0 * I00 + e1 * I01 + e2 * I02;
            const float w1 = e0 * I01 + e1 * I11 + e2 * I12;
            const float w2 = e0 * I02 + e1 * I12 + e2 * I22;
            #pragma unroll
            for (int g2 = f; g2 < 6; g2++) {
                a[f * 6 + g2] = S[q] - (w0 * E[g2 * 3 + 0] + w1 * E[g2 * 3 + 1] + w2 * E[g2 * 3 + 2]);
                q++;
            }
        }
    }
    const float trA = a[0] + a[7] + a[14] + a[21] + a[28] + a[35];

    float L[36], rAL[6];
    #pragma unroll
    for (int q = 0; q < 36; q++) L[q] = 0.0f;
    #pragma unroll
    for (int k = 0; k < 6; k++) {
        float s = a[k * 7];
        #pragma unroll
        for (int m = 0; m < k; m++) s -= L[k * 6 + m] * L[k * 6 + m];
        s = fmaxf(s, fabsf(trA) * 1e-7f + 1e-30f);
        const float rs = rsqrtf(s);
        L[k * 7] = s * rs;
        rAL[k] = rs;
        #pragma unroll
        for (int r2 = k + 1; r2 < 6; r2++) {
            float sv = a[GIX(k, r2)];
            #pragma unroll
            for (int m = 0; m < k; m++) sv -= L[r2 * 6 + m] * L[k * 6 + m];
            L[r2 * 6 + k] = sv * rs;
        }
    }

    // ---- G = L^T Cinv L (upper triangle; exploit L lower-triangular zeros) ----
    float g[36], g0[36];
    {
        float Y[36];
        #pragma unroll
        for (int j = 0; j < 6; j++) {
            Y[0 * 6 + j] = 0.5f * (L[6 + j] + L[12 + j]);
            Y[1 * 6 + j] = 0.5f * (L[0 + j] + L[12 + j]);
            Y[2 * 6 + j] = 0.5f * (L[0 + j] + L[6 + j]);
            Y[3 * 6 + j] = -0.25f * L[18 + j];
            Y[4 * 6 + j] = -0.25f * L[24 + j];
            Y[5 * 6 + j] = -0.25f * L[30 + j];
        }
        #pragma unroll
        for (int i2 = 0; i2 < 6; i2++) {
            #pragma unroll
            for (int j = i2; j < 6; j++) {
                float sv = 0.0f;
                #pragma unroll
                for (int k = 0; k < 6; k++)
                    if (k >= i2) sv += L[k * 6 + i2] * Y[k * 6 + j];   // L[k][i2]=0 for k<i2
                g[i2 * 6 + j] = sv;
                g0[i2 * 6 + j] = sv;
            }
        }
    }

    #pragma unroll
    for (int sweep = 0; sweep < 2; sweep++) {
        #pragma unroll
        for (int rd = 0; rd < 5; rd++) {
            const int JP[5][3] = {{0,1,2},{0,3,1},{0,2,1},{0,1,4},{0,2,3}};
            const int JQ[5][3] = {{5,4,3},{4,5,2},{3,4,5},{2,3,5},{1,5,4}};
            float tv[3], cv[3], sv3[3];
            #pragma unroll
            for (int i = 0; i < 3; i++) {
                const int p = JP[rd][i], qq = JQ[rd][i];
                const float rho = 2.0f * g[p * 6 + qq];
                const float tau = g[qq * 7] - g[p * 7];
                const float h2 = tau * tau + rho * rho;
                const float w = rsqrtf(h2 + 1e-38f);
                const float c2 = fmaf(0.5f * fabsf(tau), w, 0.5f);
                const float rc = rsqrtf(c2);
                const float sgn = copysignf(1.0f, tau);
                float cph = c2 * rc;
                float sph = (0.5f * rho * w * rc) * sgn;
                float tt = sph * rc;
                const bool ok = h2 > 1e-30f;
                cph = ok ? cph : 1.0f;
                sph = ok ? sph : 0.0f;
                tt  = ok ? tt  : 0.0f;
                tv[i] = tt; cv[i] = cph; sv3[i] = sph;
            }
            #pragma unroll
            for (int i = 0; i < 3; i++) {
                const int p = JP[rd][i], qq = JQ[rd][i];
                const float apq = g[p * 6 + qq];
                g[p * 7] -= tv[i] * apq;
                g[qq * 7] += tv[i] * apq;
                g[p * 6 + qq] = 0.0f;
                #pragma unroll
                for (int k = 0; k < 6; k++) {
                    if (k != p && k != qq) {
                        const float akp = g[GIX(k, p)], akq = g[GIX(k, qq)];
                        g[GIX(k, p)] = cv[i] * akp - sv3[i] * akq;
                        g[GIX(k, qq)] = sv3[i] * akp + cv[i] * akq;
                    }
                }
            }
        }
    }

    const float scale = fabsf(g0[0]) + fabsf(g0[7]) + fabsf(g0[14]) +
                        fabsf(g0[21]) + fabsf(g0[28]) + fabsf(g0[35]);
    float sig = -3e38f;
    #pragma unroll
    for (int i2 = 0; i2 < 6; i2++) {
        float row = g[i2 * 7];
        #pragma unroll
        for (int j = 0; j < 6; j++)
            if (j != i2) row += fabsf(g[GIX(i2, j)]);
        sig = fmaxf(sig, row);
    }
    sig += 1e-6f * scale + 1e-30f;

    float Hc[36], rH[6];
    #pragma unroll
    for (int q = 0; q < 36; q++) Hc[q] = 0.0f;
    #pragma unroll
    for (int k = 0; k < 6; k++) {
        float s = sig - g0[k * 7];
        #pragma unroll
        for (int m = 0; m < k; m++) s -= Hc[k * 6 + m] * Hc[k * 6 + m];
        s = fmaxf(s, 1e-8f * scale + 1e-34f);
        const float rs = rsqrtf(s);
        Hc[k * 7] = s * rs;
        rH[k] = rs;
        #pragma unroll
        for (int r2 = k + 1; r2 < 6; r2++) {
            float svv = -g0[GIX(k, r2)];
            #pragma unroll
            for (int m = 0; m < k; m++) svv -= Hc[r2 * 6 + m] * Hc[k * 6 + m];
            Hc[r2 * 6 + k] = svv * rs;
        }
    }

    // ---- 3 inverse iterations; normalize only after iterations 2 and 3 ----
    float x[6] = {1.0f, 0.81f, -0.65f, 0.43f, -0.29f, 0.17f};
    #pragma unroll
    for (int it = 0; it < 3; it++) {
        float y[6];
        #pragma unroll
        for (int k = 0; k < 6; k++) {
            float s = x[k];
            #pragma unroll
            for (int m = 0; m < k; m++) s -= Hc[k * 6 + m] * y[m];
            y[k] = s * rH[k];
        }
        #pragma unroll
        for (int k = 5; k >= 0; k--) {
            float s = y[k];
            #pragma unroll
            for (int m = 5; m > k; m--) s -= Hc[m * 6 + k] * x[m];
            x[k] = s * rH[k];
        }
        if (it >= 1) {
            const float nrm = x[0]*x[0]+x[1]*x[1]+x[2]*x[2]+x[3]*x[3]+x[4]*x[4]+x[5]*x[5];
            const float rn = fminf(rsqrtf(nrm + 1e-38f), 1e19f);
            #pragma unroll
            for (int k = 0; k < 6; k++) x[k] *= rn;
        }
    }

    float v[6];
    #pragma unroll
    for (int k = 5; k >= 0; k--) {
        float s = x[k];
        #pragma unroll
        for (int m = 5; m > k; m--) s -= L[m * 6 + k] * v[m];
        v[k] = s * rAL[k];
    }

    const float qa = v[0], qb = v[1], qc = v[2], qd = v[3], qe = v[4], qf = v[5];
    const float off2 = qd * qd + qe * qe + qf * qf;
    const float qm = (qa + qb + qc) * (1.0f / 3.0f);
    const float aa = qa - qm, bb = qb - qm, cc2 = qc - qm;
    const float p2 = aa * aa + bb * bb + cc2 * cc2 + 2.0f * off2 + 1e-36f;
    const float p2s = p2 * (1.0f / 6.0f);
    const float rp = rsqrtf(p2s);
    const float p = p2s * rp;
    const float ip = rp;
    const float b00 = aa * ip, b11 = bb * ip, b22 = cc2 * ip;
    const float b01 = qd * ip, b02 = qe * ip, b12 = qf * ip;
    const float detB = b00 * (b11 * b22 - b12 * b12)
                     - b01 * (b01 * b22 - b12 * b02)
                     + b02 * (b01 * b12 - b11 * b02);
    float rr2 = 0.5f * detB;
    rr2 = fminf(1.0f, fmaxf(-1.0f, rr2));
    const float phi = acosf(rr2) * (1.0f / 3.0f);
    const float l1 = qm + 2.0f * p * cosf(phi);
    const float l3 = qm + 2.0f * p * cosf(phi + 2.0943951023931953f);
    const float l2 = 3.0f * qm - l1 - l3;

    const float a1 = fabsf(l1), a2 = fabsf(l2), a3 = fabsf(l3);
    const float mx = fmaxf(a1, fmaxf(a2, a3));
    const float mn = fminf(a1, fminf(a2, a3));

    if (u == 0)
        out[pi * 128 + pj] = sqrtf(__fdividef(mn, mx + 1e-38f));
}

extern "C" void kernel_launch(void* const* d_in, const int* in_sizes, int n_in,
                              void* d_out, int out_size)
{
    const float* depth = (const float*)d_in[0];
    float* out = (float*)d_out;
    curvature_kernel<<<NTHREADS / 128, 128>>>(depth, out);
}

// round 16
// speedup vs baseline: 1.0468x; 1.0468x over previous
#include <cuda_runtime.h>
#include <math.h>

#define IMG 1024
#define NPATCH 16384
#define NTHREADS (NPATCH * 2)

#define GIX(i,j) (((i)<(j)) ? ((i)*6+(j)) : ((j)*6+(i)))

__global__ __launch_bounds__(128)
void curvature_kernel(const float* __restrict__ depth, float* __restrict__ out)
{
    const int t = blockIdx.x * 128 + threadIdx.x;
    const int pidx = t >> 1;        // patch index (2 lanes per patch)
    const int u = t & 1;            // lane-in-group: handles rows 4u..4u+3

    // ---- patch remap: interior patches first, boundary clustered at the end ----
    int pi, pj;
    const bool interior = (pidx < 127 * 127);
    if (interior) {
        const int r = pidx / 127;
        pi = 1 + r;
        pj = 1 + (pidx - r * 127);
    } else {
        const int b = pidx - 127 * 127;
        if (b < 128) { pi = 0; pj = b; }
        else { pi = b - 127; pj = 0; }
    }

    const int yc = 8 * pi + 3, xc = 8 * pj + 3;
    const float d36 = __ldg(&depth[yc * IMG + xc]);   // same addr across pair -> broadcast

    // ---- partial z-moments over this lane's 4 rows ----
    float Z1_10=0.f,Z1_01=0.f,Z1_20=0.f,Z1_11=0.f,Z1_02=0.f;
    float Z1_30=0.f,Z1_21=0.f,Z1_12=0.f,Z1_03=0.f;
    float Z2_00=0.f,Z2_10=0.f,Z2_01=0.f,Z2_20=0.f,Z2_11=0.f,Z2_02=0.f;
    float Z3_00=0.f,Z3_10=0.f,Z3_01=0.f;
    float Z4_00=0.f;

    if (interior) {
        const int rowbase = (8 * pi - 1) * IMG + 8 * pj;   // col 8pj, 16B aligned
        #pragma unroll
        for (int rr = 0; rr < 4; rr++) {
            const int r = 4 * u + rr;
            const float zm = __ldg(depth + rowbase - 1 + r * IMG);
            const float4 fa = __ldg(reinterpret_cast<const float4*>(depth + rowbase + r * IMG));
            const float4 fb = __ldg(reinterpret_cast<const float4*>(depth + rowbase + 4 + r * IMG));

            float z[8];
            z[0] = zm   - d36; z[1] = fa.x - d36; z[2] = fa.y - d36; z[3] = fa.z - d36;
            z[4] = fa.w - d36; z[5] = fb.x - d36; z[6] = fb.y - d36; z[7] = fb.z - d36;
            float z2[8], z3[8];
            #pragma unroll
            for (int c = 0; c < 8; c++) { z2[c] = z[c] * z[c]; z3[c] = z2[c] * z[c]; }

            float s1 = 0.f, s1a = 0.f, s1a2 = 0.f, s1a3 = 0.f;
            float s2 = 0.f, s2a = 0.f, s2a2 = 0.f;
            float s3 = 0.f, s3a = 0.f, s4 = 0.f;
            #pragma unroll
            for (int c = 0; c < 8; c++) {
                const float A = (float)(c - 4);
                const float A2 = A * A, A3 = A2 * A;
                s1   += z[c];
                s1a  = fmaf(A,  z[c], s1a);
                s1a2 = fmaf(A2, z[c], s1a2);
                s1a3 = fmaf(A3, z[c], s1a3);
                s2   += z2[c];
                s2a  = fmaf(A,  z2[c], s2a);
                s2a2 = fmaf(A2, z2[c], s2a2);
                s3   += z3[c];
                s3a  = fmaf(A,  z3[c], s3a);
                s4   = fmaf(z2[c], z2[c], s4);
            }

            const float B = (float)(r - 4);
            const float B2 = B * B, B3 = B2 * B;
            Z1_10 += s1a;                 Z1_01 = fmaf(B,  s1,   Z1_01);
            Z1_20 += s1a2;                Z1_11 = fmaf(B,  s1a,  Z1_11);
            Z1_02 = fmaf(B2, s1,  Z1_02); Z1_30 += s1a3;
            Z1_21 = fmaf(B,  s1a2, Z1_21); Z1_12 = fmaf(B2, s1a, Z1_12);
            Z1_03 = fmaf(B3, s1,  Z1_03);
            Z2_00 += s2;                  Z2_10 += s2a;
            Z2_01 = fmaf(B,  s2,  Z2_01); Z2_20 += s2a2;
            Z2_11 = fmaf(B,  s2a, Z2_11); Z2_02 = fmaf(B2, s2, Z2_02);
            Z3_00 += s3;                  Z3_10 += s3a;
            Z3_01 = fmaf(B,  s3,  Z3_01); Z4_00 += s4;
        }
    } else {
        #pragma unroll
        for (int rr = 0; rr < 4; rr++) {
            const int r = 4 * u + rr;
            const int R = 8 * pi + r;
            float z[8];
            #pragma unroll
            for (int c = 0; c < 8; c++) {
                const int C = 8 * pj + c;
                z[c] = (R == 0 || C == 0) ? 0.f
                     : __ldg(&depth[(R - 1) * IMG + (C - 1)]) - d36;
            }
            float z2[8], z3[8];
            #pragma unroll
            for (int c = 0; c < 8; c++) { z2[c] = z[c] * z[c]; z3[c] = z2[c] * z[c]; }

            float s1 = 0.f, s1a = 0.f, s1a2 = 0.f, s1a3 = 0.f;
            float s2 = 0.f, s2a = 0.f, s2a2 = 0.f;
            float s3 = 0.f, s3a = 0.f, s4 = 0.f;
            #pragma unroll
            for (int c = 0; c < 8; c++) {
                const float A = (float)(c - 4);
                const float A2 = A * A, A3 = A2 * A;
                s1   += z[c];
                s1a  = fmaf(A,  z[c], s1a);
                s1a2 = fmaf(A2, z[c], s1a2);
                s1a3 = fmaf(A3, z[c], s1a3);
                s2   += z2[c];
                s2a  = fmaf(A,  z2[c], s2a);
                s2a2 = fmaf(A2, z2[c], s2a2);
                s3   += z3[c];
                s3a  = fmaf(A,  z3[c], s3a);
                s4   = fmaf(z2[c], z2[c], s4);
            }

            const float B = (float)(r - 4);
            const float B2 = B * B, B3 = B2 * B;
            Z1_10 += s1a;                 Z1_01 = fmaf(B,  s1,   Z1_01);
            Z1_20 += s1a2;                Z1_11 = fmaf(B,  s1a,  Z1_11);
            Z1_02 = fmaf(B2, s1,  Z1_02); Z1_30 += s1a3;
            Z1_21 = fmaf(B,  s1a2, Z1_21); Z1_12 = fmaf(B2, s1a, Z1_12);
            Z1_03 = fmaf(B3, s1,  Z1_03);
            Z2_00 += s2;                  Z2_10 += s2a;
            Z2_01 = fmaf(B,  s2,  Z2_01); Z2_20 += s2a2;
            Z2_11 = fmaf(B,  s2a, Z2_11); Z2_02 = fmaf(B2, s2, Z2_02);
            Z3_00 += s3;                  Z3_10 += s3a;
            Z3_01 = fmaf(B,  s3,  Z3_01); Z4_00 += s4;
        }
    }

    // ---- single-step butterfly across the 2-lane pair ----
    #define BFLY(v) do { v += __shfl_xor_sync(0xFFFFFFFFu, v, 1); } while (0)
    BFLY(Z1_10); BFLY(Z1_01); BFLY(Z1_20); BFLY(Z1_11); BFLY(Z1_02);
    BFLY(Z1_30); BFLY(Z1_21); BFLY(Z1_12); BFLY(Z1_03);
    BFLY(Z2_00); BFLY(Z2_10); BFLY(Z2_01); BFLY(Z2_20); BFLY(Z2_11); BFLY(Z2_02);
    BFLY(Z3_00); BFLY(Z3_10); BFLY(Z3_01);
    BFLY(Z4_00);
    #undef BFLY

    // ---- assemble scatter blocks (both lanes redundantly) ----
    float S[21], E[18];
    float T00, T01, T02, T11, T12, T22;

    if (interior) {
        S[0]  = 3616.f;        S[1]  = 1936.f;        S[2]  = Z2_20;
        S[3]  = 512.f;         S[4]  = 2.f * Z1_30;   S[5]  = 2.f * Z1_21;
        S[6]  = 3616.f;        S[7]  = Z2_02;         S[8]  = 512.f;
        S[9]  = 2.f * Z1_12;   S[10] = 2.f * Z1_03;   S[11] = Z4_00;
        S[12] = 2.f * Z2_11;   S[13] = 2.f * Z3_10;   S[14] = 2.f * Z3_01;
        S[15] = 7744.f;        S[16] = 4.f * Z1_21;   S[17] = 4.f * Z1_12;
        S[18] = 4.f * Z2_20;   S[19] = 4.f * Z2_11;   S[20] = 4.f * Z2_02;

        E[0]  = -1024.f;       E[1]  = -352.f;        E[2]  = 2.f * Z1_20;
        E[3]  = -352.f;        E[4]  = -1024.f;       E[5]  = 2.f * Z1_02;
        E[6]  = 2.f * Z2_10;   E[7]  = 2.f * Z2_01;   E[8]  = 2.f * Z3_00;
        E[9]  = -704.f;        E[10] = -704.f;        E[11] = 4.f * Z1_11;
        E[12] = 4.f * Z1_20;   E[13] = 4.f * Z1_11;   E[14] = 4.f * Z2_10;
        E[15] = 4.f * Z1_11;   E[16] = 4.f * Z1_02;   E[17] = 4.f * Z2_01;

        T00 = 1408.f;  T01 = 64.f;  T02 = 4.f * Z1_10;
        T11 = 1408.f;  T12 = 4.f * Z1_01;  T22 = 4.f * Z2_00;
    } else {
        const bool top = (pi == 0), lft = (pj == 0);
        const float SA0 = lft ? 7.f : 8.f,  SA1 = lft ? 0.f : -4.f, SA2 = lft ? 28.f : 44.f;
        const float SA3 = lft ? 0.f : -64.f, SA4 = lft ? 196.f : 452.f;
        const float SB0 = top ? 7.f : 8.f,  SB1 = top ? 0.f : -4.f, SB2 = top ? 28.f : 44.f;
        const float SB3 = top ? 0.f : -64.f, SB4 = top ? 196.f : 452.f;

        S[0]  = SA4 * SB0;       S[1]  = SA2 * SB2;       S[2]  = Z2_20;
        S[3]  = 2.f * SA3 * SB1; S[4]  = 2.f * Z1_30;     S[5]  = 2.f * Z1_21;
        S[6]  = SA0 * SB4;       S[7]  = Z2_02;           S[8]  = 2.f * SA1 * SB3;
        S[9]  = 2.f * Z1_12;     S[10] = 2.f * Z1_03;     S[11] = Z4_00;
        S[12] = 2.f * Z2_11;     S[13] = 2.f * Z3_10;     S[14] = 2.f * Z3_01;
        S[15] = 4.f * SA2 * SB2; S[16] = 4.f * Z1_21;     S[17] = 4.f * Z1_12;
        S[18] = 4.f * Z2_20;     S[19] = 4.f * Z2_11;     S[20] = 4.f * Z2_02;

        E[0]  = 2.f * SA3 * SB0; E[1]  = 2.f * SA2 * SB1; E[2]  = 2.f * Z1_20;
        E[3]  = 2.f * SA1 * SB2; E[4]  = 2.f * SA0 * SB3; E[5]  = 2.f * Z1_02;
        E[6]  = 2.f * Z2_10;     E[7]  = 2.f * Z2_01;     E[8]  = 2.f * Z3_00;
        E[9]  = 4.f * SA2 * SB1; E[10] = 4.f * SA1 * SB2; E[11] = 4.f * Z1_11;
        E[12] = 4.f * Z1_20;     E[13] = 4.f * Z1_11;     E[14] = 4.f * Z2_10;
        E[15] = 4.f * Z1_11;     E[16] = 4.f * Z1_02;     E[17] = 4.f * Z2_01;

        T00 = 4.f * SA2 * SB0; T01 = 4.f * SA1 * SB1; T02 = 4.f * Z1_10;
        T11 = 4.f * SA0 * SB2; T12 = 4.f * Z1_01;     T22 = 4.f * Z2_00;

        // exact rank-1 pad correction
        const float n = (top && lft) ? 15.f : 8.f;
        const float P1 = -(float)xc, P2 = -(float)yc, P3 = -d36;
        const float dd[6] = { P1*P1, P2*P2, P3*P3, 2.f*P1*P2, 2.f*P1*P3, 2.f*P2*P3 };
        const float lv[3] = { 2.f*P1, 2.f*P2, 2.f*P3 };
        {
            int q = 0;
            #pragma unroll
            for (int f = 0; f < 6; f++) {
                const float nf = n * dd[f];
                #pragma unroll
                for (int g2 = f; g2 < 6; g2++) { S[q] = fmaf(nf, dd[g2], S[q]); q++; }
                E[f * 3 + 0] = fmaf(nf, lv[0], E[f * 3 + 0]);
                E[f * 3 + 1] = fmaf(nf, lv[1], E[f * 3 + 1]);
                E[f * 3 + 2] = fmaf(nf, lv[2], E[f * 3 + 2]);
            }
        }
        T00 = fmaf(n * lv[0], lv[0], T00); T01 = fmaf(n * lv[0], lv[1], T01);
        T02 = fmaf(n * lv[0], lv[2], T02); T11 = fmaf(n * lv[1], lv[1], T11);
        T12 = fmaf(n * lv[1], lv[2], T12); T22 = fmaf(n * lv[2], lv[2], T22);
    }

    // =================== tail (redundant on both lanes) ===================
    const float c00 = T11 * T22 - T12 * T12;
    const float c01 = T02 * T12 - T01 * T22;
    const float c02 = T01 * T12 - T02 * T11;
    const float det = T00 * c00 + T01 * c01 + T02 * c02;
    const float id = __fdividef(1.0f, det);
    const float I00 = c00 * id, I01 = c01 * id, I02 = c02 * id;
    const float I11 = (T00 * T22 - T02 * T02) * id;
    const float I12 = (T01 * T02 - T00 * T12) * id;
    const float I22 = (T00 * T11 - T01 * T01) * id;

    float a[36];
    {
        int q = 0;
        #pragma unroll
        for (int f = 0; f < 6; f++) {
            const float e0 = E[f * 3 + 0], e1 = E[f * 3 + 1], e2 = E[f * 3 + 2];
            const float w0 = e0 * I00 + e1 * I01 + e2 * I02;
            const float w1 = e0 * I01 + e1 * I11 + e2 * I12;
            const float w2 = e0 * I02 + e1 * I12 + e2 * I22;
            #pragma unroll
            for (int g2 = f; g2 < 6; g2++) {
                a[f * 6 + g2] = S[q] - (w0 * E[g2 * 3 + 0] + w1 * E[g2 * 3 + 1] + w2 * E[g2 * 3 + 2]);
                q++;
            }
        }
    }
    const float trA = a[0] + a[7] + a[14] + a[21] + a[28] + a[35];

    float L[36], rAL[6];
    #pragma unroll
    for (int q = 0; q < 36; q++) L[q] = 0.0f;
    #pragma unroll
    for (int k = 0; k < 6; k++) {
        float s = a[k * 7];
        #pragma unroll
        for (int m = 0; m < k; m++) s -= L[k * 6 + m] * L[k * 6 + m];
        s = fmaxf(s, fabsf(trA) * 1e-7f + 1e-30f);
        const float rs = rsqrtf(s);
        L[k * 7] = s * rs;
        rAL[k] = rs;
        #pragma unroll
        for (int r2 = k + 1; r2 < 6; r2++) {
            float sv = a[GIX(k, r2)];
            #pragma unroll
            for (int m = 0; m < k; m++) sv -= L[r2 * 6 + m] * L[k * 6 + m];
            L[r2 * 6 + k] = sv * rs;
        }
    }

    // ---- G = L^T Cinv L (upper triangle; L lower-triangular zeros fold away) ----
    float g[36], g0[36];
    {
        float Y[36];
        #pragma unroll
        for (int j = 0; j < 6; j++) {
            Y[0 * 6 + j] = 0.5f * (L[6 + j] + L[12 + j]);
            Y[1 * 6 + j] = 0.5f * (L[0 + j] + L[12 + j]);
            Y[2 * 6 + j] = 0.5f * (L[0 + j] + L[6 + j]);
            Y[3 * 6 + j] = -0.25f * L[18 + j];
            Y[4 * 6 + j] = -0.25f * L[24 + j];
            Y[5 * 6 + j] = -0.25f * L[30 + j];
        }
        #pragma unroll
        for (int i2 = 0; i2 < 6; i2++) {
            #pragma unroll
            for (int j = i2; j < 6; j++) {
                float sv = 0.0f;
                #pragma unroll
                for (int k = 0; k < 6; k++)
                    if (k >= i2) sv += L[k * 6 + i2] * Y[k * 6 + j];
                g[i2 * 6 + j] = sv;
                g0[i2 * 6 + j] = sv;
            }
        }
    }

    // ---- symmetric-triangle parallel-cyclic Jacobi: 2 sweeps x 5 rounds x 3 pairs ----
    #pragma unroll
    for (int sweep = 0; sweep < 2; sweep++) {
        #pragma unroll
        for (int rd = 0; rd < 5; rd++) {
            const int JP[5][3] = {{0,1,2},{0,3,1},{0,2,1},{0,1,4},{0,2,3}};
            const int JQ[5][3] = {{5,4,3},{4,5,2},{3,4,5},{2,3,5},{1,5,4}};
            float tv[3], cv[3], sv3[3];
            #pragma unroll
            for (int i = 0; i < 3; i++) {
                const int p = JP[rd][i], qq = JQ[rd][i];
                const float rho = 2.0f * g[p * 6 + qq];
                const float tau = g[qq * 7] - g[p * 7];
                const float h2 = tau * tau + rho * rho;
                const float w = rsqrtf(h2 + 1e-38f);
                const float c2 = fmaf(0.5f * fabsf(tau), w, 0.5f);
                const float rc = rsqrtf(c2);
                const float sgn = copysignf(1.0f, tau);
                float cph = c2 * rc;
                float sph = (0.5f * rho * w * rc) * sgn;
                float tt = sph * rc;
                const bool ok = h2 > 1e-30f;
                cph = ok ? cph : 1.0f;
                sph = ok ? sph : 0.0f;
                tt  = ok ? tt  : 0.0f;
                tv[i] = tt; cv[i] = cph; sv3[i] = sph;
            }
            #pragma unroll
            for (int i = 0; i < 3; i++) {
                const int p = JP[rd][i], qq = JQ[rd][i];
                const float apq = g[p * 6 + qq];
                g[p * 7] -= tv[i] * apq;
                g[qq * 7] += tv[i] * apq;
                g[p * 6 + qq] = 0.0f;
                #pragma unroll
                for (int k = 0; k < 6; k++) {
                    if (k != p && k != qq) {
                        const float akp = g[GIX(k, p)], akq = g[GIX(k, qq)];
                        g[GIX(k, p)] = cv[i] * akp - sv3[i] * akq;
                        g[GIX(k, qq)] = sv3[i] * akp + cv[i] * akq;
                    }
                }
            }
        }
    }

    // ---- sigma = Gershgorin upper bound on lambda_max ----
    const float scale = fabsf(g0[0]) + fabsf(g0[7]) + fabsf(g0[14]) +
                        fabsf(g0[21]) + fabsf(g0[28]) + fabsf(g0[35]);
    float sig = -3e38f;
    #pragma unroll
    for (int i2 = 0; i2 < 6; i2++) {
        float row = g[i2 * 7];
        #pragma unroll
        for (int j = 0; j < 6; j++)
            if (j != i2) row += fabsf(g[GIX(i2, j)]);
        sig = fmaxf(sig, row);
    }
    sig += 1e-6f * scale + 1e-30f;

    // ---- H = sig*I - G0 (PD); Cholesky + 4 inverse iterations ----
    float Hc[36], rH[6];
    #pragma unroll
    for (int q = 0; q < 36; q++) Hc[q] = 0.0f;
    #pragma unroll
    for (int k = 0; k < 6; k++) {
        float s = sig - g0[k * 7];
        #pragma unroll
        for (int m = 0; m < k; m++) s -= Hc[k * 6 + m] * Hc[k * 6 + m];
        s = fmaxf(s, 1e-8f * scale + 1e-34f);
        const float rs = rsqrtf(s);
        Hc[k * 7] = s * rs;
        rH[k] = rs;
        #pragma unroll
        for (int r2 = k + 1; r2 < 6; r2++) {
            float svv = -g0[GIX(k, r2)];
            #pragma unroll
            for (int m = 0; m < k; m++) svv -= Hc[r2 * 6 + m] * Hc[k * 6 + m];
            Hc[r2 * 6 + k] = svv * rs;
        }
    }

    // 4 inverse iterations; normalize after 1-3, final normalization is dead code
    float x[6] = {1.0f, 0.81f, -0.65f, 0.43f, -0.29f, 0.17f};
    #pragma unroll
    for (int it = 0; it < 4; it++) {
        float y[6];
        #pragma unroll
        for (int k = 0; k < 6; k++) {
            float s = x[k];
            #pragma unroll
            for (int m = 0; m < k; m++) s -= Hc[k * 6 + m] * y[m];
            y[k] = s * rH[k];
        }
        #pragma unroll
        for (int k = 5; k >= 0; k--) {
            float s = y[k];
            #pragma unroll
            for (int m = 5; m > k; m--) s -= Hc[m * 6 + k] * x[m];
            x[k] = s * rH[k];
        }
        if (it < 3) {
            const float nrm = x[0]*x[0]+x[1]*x[1]+x[2]*x[2]+x[3]*x[3]+x[4]*x[4]+x[5]*x[5];
            const float rn = rsqrtf(nrm + 1e-38f);
            #pragma unroll
            for (int k = 0; k < 6; k++) x[k] *= rn;
        }
    }

    // ---- back-substitution L^T v = x ----
    float v[6];
    #pragma unroll
    for (int k = 5; k >= 0; k--) {
        float s = x[k];
        #pragma unroll
        for (int m = 5; m > k; m--) s -= L[m * 6 + k] * v[m];
        v[k] = s * rAL[k];
    }

    // ---- closed-form symmetric 3x3 eigenvalues (branchless) ----
    const float qa = v[0], qb = v[1], qc = v[2], qd = v[3], qe = v[4], qf = v[5];
    const float off2 = qd * qd + qe * qe + qf * qf;
    const float qm = (qa + qb + qc) * (1.0f / 3.0f);
    const float aa = qa - qm, bb = qb - qm, cc2 = qc - qm;
    const float p2 = aa * aa + bb * bb + cc2 * cc2 + 2.0f * off2 + 1e-36f;
    const float p2s = p2 * (1.0f / 6.0f);
    const float rp = rsqrtf(p2s);
    const float p = p2s * rp;
    const float ip = rp;
    const float b00 = aa * ip, b11 = bb * ip, b22 = cc2 * ip;
    const float b01 = qd * ip, b02 = qe * ip, b12 = qf * ip;
    const float detB = b00 * (b11 * b22 - b12 * b12)
                     - b01 * (b01 * b22 - b12 * b02)
                     + b02 * (b01 * b12 - b11 * b02);
    float rr2 = 0.5f * detB;
    rr2 = fminf(1.0f, fmaxf(-1.0f, rr2));
    const float phi = acosf(rr2) * (1.0f / 3.0f);
    const float l1 = qm + 2.0f * p * cosf(phi);
    const float l3 = qm + 2.0f * p * cosf(phi + 2.0943951023931953f);
    const float l2 = 3.0f * qm - l1 - l3;

    const float a1 = fabsf(l1), a2 = fabsf(l2), a3 = fabsf(l3);
    const float mx = fmaxf(a1, fmaxf(a2, a3));
    const float mn = fminf(a1, fminf(a2, a3));

    if (u == 0)
        out[pi * 128 + pj] = sqrtf(__fdividef(mn, mx + 1e-38f));
}

extern "C" void kernel_launch(void* const* d_in, const int* in_sizes, int n_in,
                              void* d_out, int out_size)
{
    const float* depth = (const float*)d_in[0];
    float* out = (float*)d_out;
    curvature_kernel<<<NTHREADS / 128, 128>>>(depth, out);
}